// round 8
// baseline (speedup 1.0000x reference)
#include <cuda_runtime.h>
#include <math.h>

// ---------------------------------------------------------------------------
// GNNLoss fused single-kernel (R8): occupancy via nibble filter.
//
// R5-R7 were latency-bound at 32 warps/SM (200KB u8 table -> 1 CTA/SM, 50%
// occ; profile frozen at DRAM 46% regardless of instruction count). R8 packs
// the filter to 4 bits/node (100KB) so TWO 768-thread CTAs fit per SM
// (1536 thr = 75% occ) with a 42-reg budget -- met by a LEAN loop (no manual
// prefetch staging; rare corrections recomputed cold behind two warp votes).
//
// key[node] = (pi==0) ? 0 : (batch<<10)|pi    (u16 exact; batch<16, pi<1000)
// nib[node] = (key==0) ? 0 : 1 + (key % 15)   (4-bit, 2 nodes/byte, smem)
// nib mismatch -> target=0 certain; match -> exact u16 key LDG (~7% edges);
// true targets ~6e-5 -> hot path computes focal(t=0) unconditionally and
// corrects behind __any_sync votes.
// ---------------------------------------------------------------------------

#define MAX_NODES  262144
#define MAX_BLOCKS 512
#define NTHREADS   768

__device__ __align__(16) unsigned short g_keys[MAX_NODES];
__device__ __align__(16) unsigned char  g_nib[MAX_NODES / 2];
__device__ float g_part_es[MAX_BLOCKS];
__device__ int   g_part_ec[MAX_BLOCKS];
__device__ float g_part_ns[MAX_BLOCKS];
__device__ int   g_part_nc[MAX_BLOCKS];
__device__ unsigned int g_bar0;   // zero-init; reset by block 0 each run
__device__ unsigned int g_bar1;

__device__ __forceinline__ float rcp_approx(float x) {
    float y;
    asm("rcp.approx.f32 %0, %1;" : "=f"(y) : "f"(x));
    return y;
}

// generic focal term (node phase / tail only)
__device__ __forceinline__ float focal_term(float x, bool t) {
    float a  = fabsf(x);
    float em = __expf(-a);
    float w  = 1.0f + em;
    float L  = __logf(w);
    float q  = em * rcp_approx(w);
    bool  m  = ((x >= 0.0f) == t);
    float omp = m ? q : (1.0f - q);
    float ce  = m ? L : (a + L);
    float at  = t ? 0.25f : 0.75f;
    return at * ce * omp * omp;
}

// hot-path focal with t = 0 hard-coded
__device__ __forceinline__ float focal_t0(float x) {
    float a  = fabsf(x);
    float em = __expf(-a);
    float w  = 1.0f + em;
    float L  = __logf(w);
    float q  = em * rcp_approx(w);
    bool  neg = (x < 0.0f);
    float omp = neg ? q : (1.0f - q);
    float ce  = neg ? L : (a + L);
    return 0.75f * ce * omp * omp;
}

// rare correction: loss(x,1) - loss(x,0)   (cold path)
__device__ __forceinline__ float focal_delta(float x) {
    float a  = fabsf(x);
    float em = __expf(-a);
    float w  = 1.0f + em;
    float L  = __logf(w);
    float q  = em * rcp_approx(w);
    bool  pos = (x >= 0.0f);
    float omp1 = pos ? q : (1.0f - q);
    float ce1  = pos ? L : (a + L);
    float omp0 = pos ? (1.0f - q) : q;
    float ce0  = pos ? (a + L) : L;
    return 0.25f * ce1 * omp1 * omp1 - 0.75f * ce0 * omp0 * omp0;
}

__device__ __forceinline__ unsigned short make_key(int p, int b) {
    return (p == 0) ? (unsigned short)0 : (unsigned short)((b << 10) | p);
}

__device__ __forceinline__ unsigned int make_nib(unsigned short key) {
    return (key == 0) ? 0u : (1u + (unsigned int)(key % 15));
}

__device__ __forceinline__ unsigned int nib_at(const unsigned char* sh, int idx) {
    return (sh[idx >> 1] >> ((idx & 1) << 2)) & 0xFu;
}

__device__ __forceinline__ void block_reduce_store(float s, int c,
                                                   float* ps, int* pc) {
    #pragma unroll
    for (int o = 16; o > 0; o >>= 1) {
        s += __shfl_down_sync(0xFFFFFFFFu, s, o);
        c += __shfl_down_sync(0xFFFFFFFFu, c, o);
    }
    __shared__ float sh_s[32];
    __shared__ int   sh_c[32];
    int lane = threadIdx.x & 31;
    int wid  = threadIdx.x >> 5;
    if (lane == 0) { sh_s[wid] = s; sh_c[wid] = c; }
    __syncthreads();
    int nw = (blockDim.x + 31) >> 5;
    if (wid == 0) {
        s = (lane < nw) ? sh_s[lane] : 0.0f;
        c = (lane < nw) ? sh_c[lane] : 0;
        #pragma unroll
        for (int o = 16; o > 0; o >>= 1) {
            s += __shfl_down_sync(0xFFFFFFFFu, s, o);
            c += __shfl_down_sync(0xFFFFFFFFu, c, o);
        }
        if (lane == 0) { ps[blockIdx.x] = s; pc[blockIdx.x] = c; }
    }
    __syncthreads();
}

__device__ __forceinline__ void grid_barrier(unsigned int* bar, int nb) {
    __syncthreads();
    if (threadIdx.x == 0) {
        __threadfence();
        atomicAdd(bar, 1u);
        while (*(volatile unsigned int*)bar < (unsigned int)nb) { }
    }
    __syncthreads();
    __threadfence();
}

__global__ void __launch_bounds__(NTHREADS, 2)
fused_kernel(const float* __restrict__ edge_logits,
             const float* __restrict__ node_logits,
             const int*   __restrict__ batch,
             const int*   __restrict__ pinst,
             const int*   __restrict__ src,
             const int*   __restrict__ dst,
             int E, int N, int nvec,
             float* __restrict__ out) {
    extern __shared__ unsigned char sh[];
    int tid     = threadIdx.x;
    int nb      = gridDim.x;
    int gtid    = blockIdx.x * blockDim.x + tid;
    int gstride = nb * blockDim.x;

    // ---- phase 1: nodes in pairs (one packed nibble byte per thread) ----
    float ns = 0.0f; int nc = 0;
    {
        int npairs = N >> 1;
        const int2*   p2 = (const int2*)pinst;
        const int2*   b2 = (const int2*)batch;
        const float2* x2 = (const float2*)node_logits;
        for (int j = gtid; j < npairs; j += gstride) {
            int2   p = p2[j];
            int2   b = b2[j];
            float2 x = x2[j];
            unsigned short k0 = make_key(p.x, b.x);
            unsigned short k1 = make_key(p.y, b.y);
            g_keys[2 * j]     = k0;
            g_keys[2 * j + 1] = k1;
            g_nib[j] = (unsigned char)(make_nib(k0) | (make_nib(k1) << 4));
            bool t0 = (p.x != 0), t1 = (p.y != 0);
            ns += focal_term(x.x, t0) + focal_term(x.y, t1);
            nc += (((x.x > 0.0f) == t0) ? 1 : 0)
                + (((x.y > 0.0f) == t1) ? 1 : 0);
        }
        if ((N & 1) && gtid == 0) {
            int i = N - 1;
            unsigned short k = make_key(pinst[i], batch[i]);
            g_keys[i] = k;
            g_nib[i >> 1] = (unsigned char)make_nib(k);
            bool t = (pinst[i] != 0);
            float x = node_logits[i];
            ns += focal_term(x, t);
            nc += ((x > 0.0f) == t) ? 1 : 0;
        }
    }
    block_reduce_store(ns, nc, g_part_ns, g_part_nc);

    grid_barrier(&g_bar0, nb);   // tables complete, visible in L2

    // ---- broadcast nibble table into shared memory ----
    int nbytes = (N + 1) >> 1;
    int nw4 = (nbytes + 15) >> 4;
    const uint4* hv = (const uint4*)g_nib;
    uint4* s4 = (uint4*)sh;
    for (int i = tid; i < nw4; i += blockDim.x) s4[i] = hv[i];
    __syncthreads();

    // ---- phase 2: edges (lean loop; 48 warps/SM hide latency) ----
    const float4* elv = (const float4*)edge_logits;
    const int4*   svp = (const int4*)src;
    const int4*   dvp = (const int4*)dst;
    float es = 0.0f; int ec = 0;

    for (int i = gtid; i < nvec; i += gstride) {
        float4 x  = __ldcs(&elv[i]);
        int4   sv = __ldcs(&svp[i]);
        int4   dv = __ldcs(&dvp[i]);

        // nibble filter (smem gathers, hoisted before math)
        unsigned int n0s = nib_at(sh, sv.x), n0d = nib_at(sh, dv.x);
        unsigned int n1s = nib_at(sh, sv.y), n1d = nib_at(sh, dv.y);
        unsigned int n2s = nib_at(sh, sv.z), n2d = nib_at(sh, dv.z);
        unsigned int n3s = nib_at(sh, sv.w), n3d = nib_at(sh, dv.w);
        bool n0 = (n0s == n0d) & (n0s != 0u);
        bool n1 = (n1s == n1d) & (n1s != 0u);
        bool n2 = (n2s == n2d) & (n2s != 0u);
        bool n3 = (n3s == n3d) & (n3s != 0u);

        // unconditional t=0 loss + accuracy
        es += focal_t0(x.x);
        es += focal_t0(x.y);
        es += focal_t0(x.z);
        es += focal_t0(x.w);
        ec += (x.x <= 0.0f) ? 1 : 0;
        ec += (x.y <= 0.0f) ? 1 : 0;
        ec += (x.z <= 0.0f) ? 1 : 0;
        ec += (x.w <= 0.0f) ? 1 : 0;

        // rare corrections behind two warp votes
        unsigned int amask = __activemask();
        if (__any_sync(amask, n0 | n1 | n2 | n3)) {
            bool t0 = n0 && (__ldg(&g_keys[sv.x]) == __ldg(&g_keys[dv.x]));
            bool t1 = n1 && (__ldg(&g_keys[sv.y]) == __ldg(&g_keys[dv.y]));
            bool t2 = n2 && (__ldg(&g_keys[sv.z]) == __ldg(&g_keys[dv.z]));
            bool t3 = n3 && (__ldg(&g_keys[sv.w]) == __ldg(&g_keys[dv.w]));
            if (__any_sync(amask, t0 | t1 | t2 | t3)) {  // ~0.8% warp-iters
                if (t0) { es += focal_delta(x.x); ec += (x.x > 0.0f) ? 1 : -1; }
                if (t1) { es += focal_delta(x.y); ec += (x.y > 0.0f) ? 1 : -1; }
                if (t2) { es += focal_delta(x.z); ec += (x.z > 0.0f) ? 1 : -1; }
                if (t3) { es += focal_delta(x.w); ec += (x.w > 0.0f) ? 1 : -1; }
            }
        }
    }

    // tail edges (E % 4, or whole range if vec path disabled)
    if (blockIdx.x == 0 && tid == 0) {
        for (int e = nvec << 2; e < E; e++) {
            int sidx = src[e], didx = dst[e];
            unsigned short ks = g_keys[sidx], kd = g_keys[didx];
            bool t = (ks == kd) && (ks != 0);
            float xe = edge_logits[e];
            es += focal_term(xe, t);
            ec += ((xe > 0.0f) == t) ? 1 : 0;
        }
    }
    block_reduce_store(es, ec, g_part_es, g_part_ec);

    // ---- final barrier; block 0 reduces partials and writes outputs ----
    if (tid == 0) { __threadfence(); atomicAdd(&g_bar1, 1u); }
    if (blockIdx.x != 0) return;
    if (tid == 0) {
        while (*(volatile unsigned int*)&g_bar1 < (unsigned int)nb) { }
    }
    __syncthreads();
    __threadfence();

    if (tid < 32) {
        double des = 0.0, dns = 0.0;
        int iec = 0, inc = 0;
        for (int k = tid; k < nb; k += 32) {
            des += (double)g_part_es[k];
            dns += (double)g_part_ns[k];
            iec += g_part_ec[k];
            inc += g_part_nc[k];
        }
        #pragma unroll
        for (int o = 16; o > 0; o >>= 1) {
            des += __shfl_down_sync(0xFFFFFFFFu, des, o);
            dns += __shfl_down_sync(0xFFFFFFFFu, dns, o);
            iec += __shfl_down_sync(0xFFFFFFFFu, iec, o);
            inc += __shfl_down_sync(0xFFFFFFFFu, inc, o);
        }
        if (tid == 0) {
            float edge_loss = (float)(des / (double)E);
            float node_loss = (float)(dns / (double)N);
            out[0] = edge_loss + node_loss;  // EDGE_W = NODE_W = 1
            out[1] = edge_loss;
            out[2] = node_loss;
            out[3] = (float)((double)iec / (double)E);
            out[4] = (float)((double)inc / (double)N);
            g_bar0 = 0;                      // reset for next graph replay
            g_bar1 = 0;
        }
    }
}

extern "C" void kernel_launch(void* const* d_in, const int* in_sizes, int n_in,
                              void* d_out, int out_size) {
    const float* edge_logits = (const float*)d_in[0];
    const float* node_logits = (const float*)d_in[1];
    const int*   batch       = (const int*)d_in[2];
    const int*   pinst       = (const int*)d_in[3];
    const int*   edge_index  = (const int*)d_in[4];

    int E = in_sizes[0];
    int N = in_sizes[1];
    const int* src = edge_index;
    const int* dst = edge_index + E;
    float* out = (float*)d_out;

    int nvec = ((E & 3) == 0) ? (E >> 2) : 0;

    int smem_bytes = ((((N + 1) >> 1) + 15) >> 4) << 4;  // 100KB nibble table
    cudaFuncSetAttribute(fused_kernel,
                         cudaFuncAttributeMaxDynamicSharedMemorySize,
                         smem_bytes);

    int sm_count = 148;
    cudaDeviceGetAttribute(&sm_count, cudaDevAttrMultiProcessorCount, 0);

    // size the grid by ACTUAL occupancy so the grid barrier cannot deadlock
    int per_sm = 1;
    cudaOccupancyMaxActiveBlocksPerMultiprocessor(&per_sm, fused_kernel,
                                                  NTHREADS, smem_bytes);
    if (per_sm < 1) per_sm = 1;
    int nblocks = sm_count * per_sm;
    if (nblocks > MAX_BLOCKS) nblocks = MAX_BLOCKS;

    fused_kernel<<<nblocks, NTHREADS, smem_bytes>>>(edge_logits, node_logits,
                                                    batch, pinst, src, dst,
                                                    E, N, nvec, out);
}

// round 9
// speedup vs baseline: 1.2362x; 1.2362x over previous
#include <cuda_runtime.h>
#include <math.h>

// ---------------------------------------------------------------------------
// GNNLoss fused single-kernel (R9): no-spill register budget + deep MLP.
//
// Diagnosis R5-R8: every 1024-thr/2-CTA variant compiled AT its reg ceiling
// (64 / 42) -> ptxas spills -> 2-3x instruction inflation (L1% was spill
// traffic). R9 runs 768 threads x 1 CTA/SM: 85-reg budget fits the natural
// live set with slack. MLP comes from a 2-chunk unroll (6 outstanding
// LDG.128 per warp-iter = 18KB in flight per SM at 24 warps), not from
// spill-prone pipelining.
//
// key[node]  = (pi==0) ? 0 : (batch<<10)|pi     (u16 exact)
// hash[node] = (key==0) ? 0 : (key % 255) + 1   (u8 filter, 200KB smem)
// Hot path: focal(t=0) unconditionally (P(t=1)~6e-5); corrections behind
// two warp votes (hash-pass ~42% of warp-iters, true-match ~0.8%).
// ---------------------------------------------------------------------------

#define MAX_NODES  262144
#define MAX_BLOCKS 512
#define NTHREADS   768

__device__ __align__(16) unsigned short g_keys[MAX_NODES];
__device__ __align__(16) unsigned char  g_hash[MAX_NODES];
__device__ float g_part_es[MAX_BLOCKS];
__device__ int   g_part_ec[MAX_BLOCKS];
__device__ float g_part_ns[MAX_BLOCKS];
__device__ int   g_part_nc[MAX_BLOCKS];
__device__ unsigned int g_bar0;   // zero-init; reset by block 0 each run
__device__ unsigned int g_bar1;

__device__ __forceinline__ float rcp_approx(float x) {
    float y;
    asm("rcp.approx.f32 %0, %1;" : "=f"(y) : "f"(x));
    return y;
}

// generic focal term (node phase / tail only)
__device__ __forceinline__ float focal_term(float x, bool t) {
    float a  = fabsf(x);
    float em = __expf(-a);
    float w  = 1.0f + em;
    float L  = __logf(w);
    float q  = em * rcp_approx(w);
    bool  m  = ((x >= 0.0f) == t);
    float omp = m ? q : (1.0f - q);
    float ce  = m ? L : (a + L);
    float at  = t ? 0.25f : 0.75f;
    return at * ce * omp * omp;
}

// hot-path focal with t = 0 hard-coded
__device__ __forceinline__ float focal_t0(float x) {
    float a  = fabsf(x);
    float em = __expf(-a);
    float w  = 1.0f + em;
    float L  = __logf(w);
    float q  = em * rcp_approx(w);
    bool  neg = (x < 0.0f);
    float omp = neg ? q : (1.0f - q);
    float ce  = neg ? L : (a + L);
    return 0.75f * ce * omp * omp;
}

// rare correction: loss(x,1) - loss(x,0)   (cold path, recomputed)
__device__ __forceinline__ float focal_delta(float x) {
    float a  = fabsf(x);
    float em = __expf(-a);
    float w  = 1.0f + em;
    float L  = __logf(w);
    float q  = em * rcp_approx(w);
    bool  pos = (x >= 0.0f);
    float omp1 = pos ? q : (1.0f - q);
    float ce1  = pos ? L : (a + L);
    float omp0 = pos ? (1.0f - q) : q;
    float ce0  = pos ? (a + L) : L;
    return 0.25f * ce1 * omp1 * omp1 - 0.75f * ce0 * omp0 * omp0;
}

__device__ __forceinline__ void block_reduce_store(float s, int c,
                                                   float* ps, int* pc) {
    #pragma unroll
    for (int o = 16; o > 0; o >>= 1) {
        s += __shfl_down_sync(0xFFFFFFFFu, s, o);
        c += __shfl_down_sync(0xFFFFFFFFu, c, o);
    }
    __shared__ float sh_s[32];
    __shared__ int   sh_c[32];
    int lane = threadIdx.x & 31;
    int wid  = threadIdx.x >> 5;
    if (lane == 0) { sh_s[wid] = s; sh_c[wid] = c; }
    __syncthreads();
    int nw = (blockDim.x + 31) >> 5;
    if (wid == 0) {
        s = (lane < nw) ? sh_s[lane] : 0.0f;
        c = (lane < nw) ? sh_c[lane] : 0;
        #pragma unroll
        for (int o = 16; o > 0; o >>= 1) {
            s += __shfl_down_sync(0xFFFFFFFFu, s, o);
            c += __shfl_down_sync(0xFFFFFFFFu, c, o);
        }
        if (lane == 0) { ps[blockIdx.x] = s; pc[blockIdx.x] = c; }
    }
    __syncthreads();
}

__device__ __forceinline__ void grid_barrier(unsigned int* bar, int nb) {
    __syncthreads();
    if (threadIdx.x == 0) {
        __threadfence();
        atomicAdd(bar, 1u);
        while (*(volatile unsigned int*)bar < (unsigned int)nb) { }
    }
    __syncthreads();
    __threadfence();
}

// process one vec4 chunk: unconditional t=0 math + two-vote corrections
__device__ __forceinline__ void process_chunk(const unsigned char* sh,
                                              float4 x, int4 sv, int4 dv,
                                              float& es, int& ec) {
    unsigned int h0s = sh[sv.x], h0d = sh[dv.x];
    unsigned int h1s = sh[sv.y], h1d = sh[dv.y];
    unsigned int h2s = sh[sv.z], h2d = sh[dv.z];
    unsigned int h3s = sh[sv.w], h3d = sh[dv.w];
    bool n0 = (h0s == h0d) & (h0s != 0u);
    bool n1 = (h1s == h1d) & (h1s != 0u);
    bool n2 = (h2s == h2d) & (h2s != 0u);
    bool n3 = (h3s == h3d) & (h3s != 0u);

    es += focal_t0(x.x);
    es += focal_t0(x.y);
    es += focal_t0(x.z);
    es += focal_t0(x.w);
    ec += (x.x <= 0.0f) ? 1 : 0;
    ec += (x.y <= 0.0f) ? 1 : 0;
    ec += (x.z <= 0.0f) ? 1 : 0;
    ec += (x.w <= 0.0f) ? 1 : 0;

    unsigned int amask = __activemask();
    if (__any_sync(amask, n0 | n1 | n2 | n3)) {
        bool t0 = n0 && (__ldg(&g_keys[sv.x]) == __ldg(&g_keys[dv.x]));
        bool t1 = n1 && (__ldg(&g_keys[sv.y]) == __ldg(&g_keys[dv.y]));
        bool t2 = n2 && (__ldg(&g_keys[sv.z]) == __ldg(&g_keys[dv.z]));
        bool t3 = n3 && (__ldg(&g_keys[sv.w]) == __ldg(&g_keys[dv.w]));
        if (__any_sync(amask, t0 | t1 | t2 | t3)) {      // ~0.8% warp-iters
            if (t0) { es += focal_delta(x.x); ec += (x.x > 0.0f) ? 1 : -1; }
            if (t1) { es += focal_delta(x.y); ec += (x.y > 0.0f) ? 1 : -1; }
            if (t2) { es += focal_delta(x.z); ec += (x.z > 0.0f) ? 1 : -1; }
            if (t3) { es += focal_delta(x.w); ec += (x.w > 0.0f) ? 1 : -1; }
        }
    }
}

__global__ void __launch_bounds__(NTHREADS, 1)
fused_kernel(const float* __restrict__ edge_logits,
             const float* __restrict__ node_logits,
             const int*   __restrict__ batch,
             const int*   __restrict__ pinst,
             const int*   __restrict__ src,
             const int*   __restrict__ dst,
             int E, int N, int nvec,
             float* __restrict__ out) {
    extern __shared__ unsigned char sh[];
    int tid     = threadIdx.x;
    int nb      = gridDim.x;
    int gtid    = blockIdx.x * blockDim.x + tid;
    int gstride = nb * blockDim.x;

    // ---- phase 1: nodes (build key + hash tables, node loss/acc) ----
    float ns = 0.0f; int nc = 0;
    for (int i = gtid; i < N; i += gstride) {
        int p = pinst[i];
        int b = batch[i];
        unsigned short key = (p == 0) ? (unsigned short)0
                                      : (unsigned short)((b << 10) | p);
        g_keys[i] = key;
        g_hash[i] = (key == 0) ? (unsigned char)0
                               : (unsigned char)((key % 255) + 1);
        float x = node_logits[i];
        bool  t = (p != 0);
        ns += focal_term(x, t);
        nc += ((x > 0.0f) == t) ? 1 : 0;
    }
    block_reduce_store(ns, nc, g_part_ns, g_part_nc);

    grid_barrier(&g_bar0, nb);   // tables complete, visible in L2

    // ---- broadcast hash table into shared memory ----
    int nw4 = (N + 15) >> 4;
    const uint4* hv = (const uint4*)g_hash;
    uint4* s4 = (uint4*)sh;
    for (int i = tid; i < nw4; i += blockDim.x) s4[i] = hv[i];
    __syncthreads();

    // ---- phase 2: edges, 2-chunk unroll (6 LDG.128 in flight/warp) ----
    const float4* elv = (const float4*)edge_logits;
    const int4*   svp = (const int4*)src;
    const int4*   dvp = (const int4*)dst;
    float es = 0.0f; int ec = 0;

    for (int i = gtid; i < nvec; i += 2 * gstride) {
        int j = i + gstride;
        bool vj = (j < nvec);

        // issue all loads up front (independent; fills the LSU queue)
        float4 xa  = __ldcs(&elv[i]);
        int4   sva = __ldcs(&svp[i]);
        int4   dva = __ldcs(&dvp[i]);
        float4 xb;  int4 svb, dvb;
        if (vj) {
            xb  = __ldcs(&elv[j]);
            svb = __ldcs(&svp[j]);
            dvb = __ldcs(&dvp[j]);
        }

        process_chunk(sh, xa, sva, dva, es, ec);
        if (vj) process_chunk(sh, xb, svb, dvb, es, ec);
    }

    // tail edges (E % 4, or whole range if vec path disabled)
    if (blockIdx.x == 0 && tid == 0) {
        for (int e = nvec << 2; e < E; e++) {
            int sidx = src[e], didx = dst[e];
            unsigned short ks = g_keys[sidx], kd = g_keys[didx];
            bool t = (ks == kd) && (ks != 0);
            float xe = edge_logits[e];
            es += focal_term(xe, t);
            ec += ((xe > 0.0f) == t) ? 1 : 0;
        }
    }
    block_reduce_store(es, ec, g_part_es, g_part_ec);

    // ---- final barrier; block 0 reduces partials and writes outputs ----
    if (tid == 0) { __threadfence(); atomicAdd(&g_bar1, 1u); }
    if (blockIdx.x != 0) return;
    if (tid == 0) {
        while (*(volatile unsigned int*)&g_bar1 < (unsigned int)nb) { }
    }
    __syncthreads();
    __threadfence();

    if (tid < 32) {
        double des = 0.0, dns = 0.0;
        int iec = 0, inc = 0;
        for (int k = tid; k < nb; k += 32) {
            des += (double)g_part_es[k];
            dns += (double)g_part_ns[k];
            iec += g_part_ec[k];
            inc += g_part_nc[k];
        }
        #pragma unroll
        for (int o = 16; o > 0; o >>= 1) {
            des += __shfl_down_sync(0xFFFFFFFFu, des, o);
            dns += __shfl_down_sync(0xFFFFFFFFu, dns, o);
            iec += __shfl_down_sync(0xFFFFFFFFu, iec, o);
            inc += __shfl_down_sync(0xFFFFFFFFu, inc, o);
        }
        if (tid == 0) {
            float edge_loss = (float)(des / (double)E);
            float node_loss = (float)(dns / (double)N);
            out[0] = edge_loss + node_loss;  // EDGE_W = NODE_W = 1
            out[1] = edge_loss;
            out[2] = node_loss;
            out[3] = (float)((double)iec / (double)E);
            out[4] = (float)((double)inc / (double)N);
            g_bar0 = 0;                      // reset for next graph replay
            g_bar1 = 0;
        }
    }
}

extern "C" void kernel_launch(void* const* d_in, const int* in_sizes, int n_in,
                              void* d_out, int out_size) {
    const float* edge_logits = (const float*)d_in[0];
    const float* node_logits = (const float*)d_in[1];
    const int*   batch       = (const int*)d_in[2];
    const int*   pinst       = (const int*)d_in[3];
    const int*   edge_index  = (const int*)d_in[4];

    int E = in_sizes[0];
    int N = in_sizes[1];
    const int* src = edge_index;
    const int* dst = edge_index + E;
    float* out = (float*)d_out;

    int nvec = ((E & 3) == 0) ? (E >> 2) : 0;

    int smem_bytes = ((N + 15) >> 4) << 4;   // 8-bit hash table, 200KB
    cudaFuncSetAttribute(fused_kernel,
                         cudaFuncAttributeMaxDynamicSharedMemorySize,
                         smem_bytes);

    int sm_count = 148;
    cudaDeviceGetAttribute(&sm_count, cudaDevAttrMultiProcessorCount, 0);

    // size the grid by ACTUAL occupancy so the grid barrier cannot deadlock
    int per_sm = 1;
    cudaOccupancyMaxActiveBlocksPerMultiprocessor(&per_sm, fused_kernel,
                                                  NTHREADS, smem_bytes);
    if (per_sm < 1) per_sm = 1;
    int nblocks = sm_count * per_sm;
    if (nblocks > MAX_BLOCKS) nblocks = MAX_BLOCKS;

    fused_kernel<<<nblocks, NTHREADS, smem_bytes>>>(edge_logits, node_logits,
                                                    batch, pinst, src, dst,
                                                    E, N, nvec, out);
}